// round 13
// baseline (speedup 1.0000x reference)
#include <cuda_runtime.h>
#include <cuda_fp16.h>
#include <cstdint>

// ---------------------------------------------------------------------------
// MLMM electrostatics.
// E(p) = KE * q_v * ( q_u*chi - chi^3*(r.mu) + chi^5 * sum(O * Q') )
// with Q' = Q - (trQ/3) I (traceless), Q'22 = -(Q'00+Q'11).
//
// Gather record per ML atom: 32 bytes, 32B-aligned (ONE L2 sector), fetched
// with a single Blackwell LDG.E.256 (ld.global.nc.v8.f32).
//
// R13 = R11 (warp-local staging, champion) with the staging LDG+STS replaced
// by cp.async.cg (one instruction, no register round-trip, no separate STS
// wavefront, L1-bypass) + __ldcg on the dist/idx streams. Streaming data no
// longer pollutes L1, which now holds the gather working set (g_packed+q_mm).
// No mbarriers (R12's per-warp TMA overhead killed it); completion is
// per-thread cp.async.wait_group + __syncwarp.
// ---------------------------------------------------------------------------

#define NML_MAX 50000
#define KE_CONST 14.399645351950548f
#define CUTOFF_A 10.0f
#define BLK 256

// [2*u] : float4 {q, mu}; [2*u+1] : 8 fp16 Q' components
__device__ __align__(32) float4 g_packed[NML_MAX * 2];

__global__ void mlmm_prep_kernel(const float* __restrict__ q_ml,
                                 const float* __restrict__ mu,
                                 const float* __restrict__ Q,
                                 const float* __restrict__ e0,
                                 float* __restrict__ out,
                                 int nml) {
    int u = blockIdx.x * blockDim.x + threadIdx.x;
    if (u >= nml) return;

    out[u] = e0[u];

    float m0 = mu[3 * u + 0];
    float m1 = mu[3 * u + 1];
    float m2 = mu[3 * u + 2];

    float Qv[9];
#pragma unroll
    for (int k = 0; k < 9; k++) Qv[k] = Q[9 * u + k];
    float third_tr = (Qv[0] + Qv[4] + Qv[8]) * (1.0f / 3.0f);

    float t00 = Qv[0] - third_tr;
    float t11 = Qv[4] - third_tr;

    g_packed[2 * u + 0] = make_float4(q_ml[u], m0, m1, m2);

    __half2 h0 = __floats2half2_rn(t00,   Qv[1]);
    __half2 h1 = __floats2half2_rn(Qv[2], Qv[3]);
    __half2 h2 = __floats2half2_rn(t11,   Qv[5]);
    __half2 h3 = __floats2half2_rn(Qv[6], Qv[7]);

    uint4 packed;
    packed.x = *reinterpret_cast<unsigned int*>(&h0);
    packed.y = *reinterpret_cast<unsigned int*>(&h1);
    packed.z = *reinterpret_cast<unsigned int*>(&h2);
    packed.w = *reinterpret_cast<unsigned int*>(&h3);
    reinterpret_cast<uint4*>(g_packed)[2 * u + 1] = packed;
}

__device__ __forceinline__ uint32_t smem_u32(const void* p) {
    uint32_t a;
    asm("{ .reg .u64 t; cvta.to.shared.u64 t, %1; cvt.u32.u64 %0, t; }"
        : "=r"(a) : "l"(p));
    return a;
}

__global__ void __launch_bounds__(BLK)
mlmm_pair_kernel(const float* __restrict__ dist,
                 const float* __restrict__ vec,
                 const float* __restrict__ outer,
                 const int* __restrict__ idx_u,
                 const int* __restrict__ idx_v,
                 const float* __restrict__ q_mm,
                 float* __restrict__ out,
                 int n) {
    __shared__ __align__(16) float s_vec[BLK * 3];   // per-warp chunks: 96 floats
    __shared__ __align__(16) float s_out[BLK * 9];   // per-warp chunks: 288 floats

    int base = blockIdx.x * BLK;
    int cnt  = n - base;
    if (cnt > BLK) cnt = BLK;

    int tid  = threadIdx.x;
    int lane = tid & 31;
    int w    = tid >> 5;

    int wbase = base + 32 * w;
    int wcnt  = cnt - 32 * w;
    if (wcnt > 32) wcnt = 32;

    float* sv = s_vec + 96 * w;
    float* so = s_out + 288 * w;
    bool fullwarp = (wcnt == 32);

    // ---- phase 0: warp-local async staging (cp.async.cg: no STS, L1 bypass) ----
    if (fullwarp) {
        uint32_t sva = smem_u32(sv);
        uint32_t soa = smem_u32(so);
        const char* gv = (const char*)(vec + 3 * wbase);
        const char* go = (const char*)(outer + 9 * wbase);

        if (lane < 24) {
            asm volatile("cp.async.cg.shared.global [%0], [%1], 16;"
                         :: "r"(sva + lane * 16u), "l"(gv + lane * 16) : "memory");
        }
#pragma unroll
        for (int k = 0; k < 3; k++) {
            int t = lane + 32 * k;
            if (t < 72) {
                asm volatile("cp.async.cg.shared.global [%0], [%1], 16;"
                             :: "r"(soa + t * 16u), "l"(go + t * 16) : "memory");
            }
        }
        asm volatile("cp.async.commit_group;" ::: "memory");
    }

    // ---- phase 1: per-thread loads, issued while cp.async streams ----
    int   i = base + tid;
    float d = 1e30f;
    int   u = 0, v = 0;
    if (tid < cnt) {
        d = __ldcg(dist + i);     // L1-bypass: stream read once
        u = __ldcg(idx_u + i);
        v = __ldcg(idx_v + i);
    }
    bool m = (d <= CUTOFF_A);

    float4 p0 = make_float4(0.f, 0.f, 0.f, 0.f);
    uint4  ph = make_uint4(0u, 0u, 0u, 0u);
    float  qv = 0.f;
    if (m) {
        // single 256-bit gather of the whole 32B record (Blackwell LDG.E.256)
        const float* rec = reinterpret_cast<const float*>(g_packed + 2 * u);
        float f0, f1, f2, f3, f4, f5, f6, f7;
        asm volatile(
            "ld.global.nc.v8.f32 {%0, %1, %2, %3, %4, %5, %6, %7}, [%8];"
            : "=f"(f0), "=f"(f1), "=f"(f2), "=f"(f3),
              "=f"(f4), "=f"(f5), "=f"(f6), "=f"(f7)
            : "l"(rec));
        p0 = make_float4(f0, f1, f2, f3);
        ph = make_uint4(__float_as_uint(f4), __float_as_uint(f5),
                        __float_as_uint(f6), __float_as_uint(f7));
        qv = KE_CONST * __ldg(q_mm + v);
    }

    // ---- phase 2: wait for this warp's staged tile ----
    if (fullwarp) {
        asm volatile("cp.async.wait_group 0;" ::: "memory");
        __syncwarp();
    } else if (wcnt > 0) {
        for (int t = lane; t < wcnt * 3; t += 32) sv[t] = vec[3 * wbase + t];
        for (int t = lane; t < wcnt * 9; t += 32) so[t] = outer[9 * wbase + t];
        __syncwarp();
    }

    if (!m) return;

    // ---- phase 3: math + scatter ----
    float r0 = sv[3 * lane + 0];
    float r1 = sv[3 * lane + 1];
    float r2 = sv[3 * lane + 2];

    const float* op = so + 9 * lane;
    float o00 = op[0], o01 = op[1], o02 = op[2];
    float o10 = op[3], o11 = op[4], o12 = op[5];
    float o20 = op[6], o21 = op[7], o22 = op[8];

    float chi  = __fdividef(1.0f, d);
    float chi2 = chi * chi;
    float chi3 = chi2 * chi;
    float chi5 = chi3 * chi2;

    // charge-charge
    float e = p0.x * chi;

    // dipole: - chi^3 * (r . mu)
    e -= chi3 * (r0 * p0.y + r1 * p0.z + r2 * p0.w);

    // quadrupole: + chi^5 * sum(O * Q'), Q'22 = -(Q'00 + Q'11)
    float2 c0 = __half22float2(*reinterpret_cast<__half2*>(&ph.x)); // t00, Q01
    float2 c1 = __half22float2(*reinterpret_cast<__half2*>(&ph.y)); // Q02, Q10
    float2 c2 = __half22float2(*reinterpret_cast<__half2*>(&ph.z)); // t11, Q12
    float2 c3 = __half22float2(*reinterpret_cast<__half2*>(&ph.w)); // Q20, Q21

    float dot9 = c0.x * (o00 - o22)
               + c2.x * (o11 - o22)
               + c0.y * o01 + c1.x * o02 + c1.y * o10
               + c2.y * o12 + c3.x * o20 + c3.y * o21;
    e += chi5 * dot9;

    e *= qv;

    atomicAdd(out + u, e);
}

extern "C" void kernel_launch(void* const* d_in, const int* in_sizes, int n_in,
                              void* d_out, int out_size) {
    const float* q_ml  = (const float*)d_in[0];  // [NML]
    const float* q_mm  = (const float*)d_in[1];  // [NMM]
    const float* mu    = (const float*)d_in[2];  // [NML,3]
    const float* Q     = (const float*)d_in[3];  // [NML,3,3]
    const float* e0    = (const float*)d_in[4];  // [NML]
    const float* dist  = (const float*)d_in[5];  // [P]
    const float* vec   = (const float*)d_in[6];  // [P,3]
    const float* outer = (const float*)d_in[7];  // [P,3,3]
    const int*   idx_u = (const int*)d_in[8];    // [P] int32
    const int*   idx_v = (const int*)d_in[9];    // [P] int32

    float* out = (float*)d_out;

    int nml = in_sizes[0];
    int P   = in_sizes[5];

    {
        int threads = 256;
        int blocks  = (nml + threads - 1) / threads;
        mlmm_prep_kernel<<<blocks, threads>>>(q_ml, mu, Q, e0, out, nml);
    }
    {
        int blocks = (P + BLK - 1) / BLK;
        mlmm_pair_kernel<<<blocks, BLK>>>(dist, vec, outer, idx_u, idx_v,
                                          q_mm, out, P);
    }
}

// round 14
// speedup vs baseline: 1.0707x; 1.0707x over previous
#include <cuda_runtime.h>
#include <cuda_fp16.h>
#include <cstdint>

// ---------------------------------------------------------------------------
// MLMM electrostatics.
// E(p) = KE * q_v * ( q_u*chi - chi^3*(r.mu) + chi^5 * sum(O * Q') )
// with Q' = Q - (trQ/3) I (traceless), Q'22 = -(Q'00+Q'11).
//
// Gather record per ML atom: 32 bytes, 32B-aligned (ONE L2 sector), fetched
// with a single Blackwell LDG.E.256 (ld.global.nc.v8.f32).
//
// R14 = R11 (champion: warp-local LDG.128+STS staging, early gather issue)
// + L1 cache hygiene: ALL streaming accesses (staging loads, dist, idx_u,
// idx_v) use .cg (L2-only), so the 544MB stream no longer evicts the gather
// working set (g_packed 1.6MB + q_mm 0.8MB) from L1. Gathers keep .nc/.ca.
// cp.async/TMA staging variants measured worse (R12/R13) - plain LDG+STS it is.
// ---------------------------------------------------------------------------

#define NML_MAX 50000
#define KE_CONST 14.399645351950548f
#define CUTOFF_A 10.0f
#define BLK 256

// [2*u] : float4 {q, mu}; [2*u+1] : 8 fp16 Q' components
__device__ __align__(32) float4 g_packed[NML_MAX * 2];

__global__ void mlmm_prep_kernel(const float* __restrict__ q_ml,
                                 const float* __restrict__ mu,
                                 const float* __restrict__ Q,
                                 const float* __restrict__ e0,
                                 float* __restrict__ out,
                                 int nml) {
    int u = blockIdx.x * blockDim.x + threadIdx.x;
    if (u >= nml) return;

    out[u] = e0[u];

    float m0 = mu[3 * u + 0];
    float m1 = mu[3 * u + 1];
    float m2 = mu[3 * u + 2];

    float Qv[9];
#pragma unroll
    for (int k = 0; k < 9; k++) Qv[k] = Q[9 * u + k];
    float third_tr = (Qv[0] + Qv[4] + Qv[8]) * (1.0f / 3.0f);

    float t00 = Qv[0] - third_tr;
    float t11 = Qv[4] - third_tr;

    g_packed[2 * u + 0] = make_float4(q_ml[u], m0, m1, m2);

    __half2 h0 = __floats2half2_rn(t00,   Qv[1]);
    __half2 h1 = __floats2half2_rn(Qv[2], Qv[3]);
    __half2 h2 = __floats2half2_rn(t11,   Qv[5]);
    __half2 h3 = __floats2half2_rn(Qv[6], Qv[7]);

    uint4 packed;
    packed.x = *reinterpret_cast<unsigned int*>(&h0);
    packed.y = *reinterpret_cast<unsigned int*>(&h1);
    packed.z = *reinterpret_cast<unsigned int*>(&h2);
    packed.w = *reinterpret_cast<unsigned int*>(&h3);
    reinterpret_cast<uint4*>(g_packed)[2 * u + 1] = packed;
}

__global__ void __launch_bounds__(BLK)
mlmm_pair_kernel(const float* __restrict__ dist,
                 const float* __restrict__ vec,
                 const float* __restrict__ outer,
                 const int* __restrict__ idx_u,
                 const int* __restrict__ idx_v,
                 const float* __restrict__ q_mm,
                 float* __restrict__ out,
                 int n) {
    __shared__ __align__(16) float s_vec[BLK * 3];   // per-warp chunks: 96 floats
    __shared__ __align__(16) float s_out[BLK * 9];   // per-warp chunks: 288 floats

    int base = blockIdx.x * BLK;
    int cnt  = n - base;
    if (cnt > BLK) cnt = BLK;

    int tid  = threadIdx.x;
    int lane = tid & 31;
    int w    = tid >> 5;

    // ---- phase 1: per-thread loads, issued EARLY and in parallel ----
    int   i = base + tid;
    float d = 1e30f;
    int   u = 0, v = 0;
    if (tid < cnt) {
        d = __ldcg(dist + i);    // stream: L2-only, keep L1 for gathers
        u = __ldcg(idx_u + i);
        v = __ldcg(idx_v + i);
    }
    bool m = (d <= CUTOFF_A);

    float4 p0 = make_float4(0.f, 0.f, 0.f, 0.f);
    uint4  ph = make_uint4(0u, 0u, 0u, 0u);
    float  qv = 0.f;
    if (m) {
        // single 256-bit gather of the whole 32B record (Blackwell LDG.E.256)
        const float* rec = reinterpret_cast<const float*>(g_packed + 2 * u);
        float f0, f1, f2, f3, f4, f5, f6, f7;
        asm volatile(
            "ld.global.nc.v8.f32 {%0, %1, %2, %3, %4, %5, %6, %7}, [%8];"
            : "=f"(f0), "=f"(f1), "=f"(f2), "=f"(f3),
              "=f"(f4), "=f"(f5), "=f"(f6), "=f"(f7)
            : "l"(rec));
        p0 = make_float4(f0, f1, f2, f3);
        ph = make_uint4(__float_as_uint(f4), __float_as_uint(f5),
                        __float_as_uint(f6), __float_as_uint(f7));
        qv = KE_CONST * __ldg(q_mm + v);
    }

    // ---- phase 2: WARP-LOCAL staging of this warp's 32 pairs (L2-only) ----
    int wbase = base + 32 * w;       // first pair of this warp
    int wcnt  = cnt - 32 * w;        // pairs this warp owns
    if (wcnt > 32) wcnt = 32;

    float* sv = s_vec + 96 * w;      // 96 floats  (32 pairs x 3)
    float* so = s_out + 288 * w;     // 288 floats (32 pairs x 9)

    if (wcnt == 32) {
        const float4* v4 = (const float4*)(vec + 3 * wbase);
        if (lane < 24) reinterpret_cast<float4*>(sv)[lane] = __ldcg(v4 + lane);

        const float4* o4 = (const float4*)(outer + 9 * wbase);
#pragma unroll
        for (int t = lane; t < 72; t += 32)
            reinterpret_cast<float4*>(so)[t] = __ldcg(o4 + t);
    } else if (wcnt > 0) {
        for (int t = lane; t < wcnt * 3; t += 32) sv[t] = __ldcg(vec + 3 * wbase + t);
        for (int t = lane; t < wcnt * 9; t += 32) so[t] = __ldcg(outer + 9 * wbase + t);
    }
    __syncwarp();

    if (!m) return;

    // ---- phase 3: math + scatter ----
    float r0 = sv[3 * lane + 0];
    float r1 = sv[3 * lane + 1];
    float r2 = sv[3 * lane + 2];

    const float* op = so + 9 * lane;
    float o00 = op[0], o01 = op[1], o02 = op[2];
    float o10 = op[3], o11 = op[4], o12 = op[5];
    float o20 = op[6], o21 = op[7], o22 = op[8];

    float chi  = __fdividef(1.0f, d);
    float chi2 = chi * chi;
    float chi3 = chi2 * chi;
    float chi5 = chi3 * chi2;

    // charge-charge
    float e = p0.x * chi;

    // dipole: - chi^3 * (r . mu)
    e -= chi3 * (r0 * p0.y + r1 * p0.z + r2 * p0.w);

    // quadrupole: + chi^5 * sum(O * Q'), Q'22 = -(Q'00 + Q'11)
    float2 c0 = __half22float2(*reinterpret_cast<__half2*>(&ph.x)); // t00, Q01
    float2 c1 = __half22float2(*reinterpret_cast<__half2*>(&ph.y)); // Q02, Q10
    float2 c2 = __half22float2(*reinterpret_cast<__half2*>(&ph.z)); // t11, Q12
    float2 c3 = __half22float2(*reinterpret_cast<__half2*>(&ph.w)); // Q20, Q21

    float dot9 = c0.x * (o00 - o22)
               + c2.x * (o11 - o22)
               + c0.y * o01 + c1.x * o02 + c1.y * o10
               + c2.y * o12 + c3.x * o20 + c3.y * o21;
    e += chi5 * dot9;

    e *= qv;

    atomicAdd(out + u, e);
}

extern "C" void kernel_launch(void* const* d_in, const int* in_sizes, int n_in,
                              void* d_out, int out_size) {
    const float* q_ml  = (const float*)d_in[0];  // [NML]
    const float* q_mm  = (const float*)d_in[1];  // [NMM]
    const float* mu    = (const float*)d_in[2];  // [NML,3]
    const float* Q     = (const float*)d_in[3];  // [NML,3,3]
    const float* e0    = (const float*)d_in[4];  // [NML]
    const float* dist  = (const float*)d_in[5];  // [P]
    const float* vec   = (const float*)d_in[6];  // [P,3]
    const float* outer = (const float*)d_in[7];  // [P,3,3]
    const int*   idx_u = (const int*)d_in[8];    // [P] int32
    const int*   idx_v = (const int*)d_in[9];    // [P] int32

    float* out = (float*)d_out;

    int nml = in_sizes[0];
    int P   = in_sizes[5];

    {
        int threads = 256;
        int blocks  = (nml + threads - 1) / threads;
        mlmm_prep_kernel<<<blocks, threads>>>(q_ml, mu, Q, e0, out, nml);
    }
    {
        int blocks = (P + BLK - 1) / BLK;
        mlmm_pair_kernel<<<blocks, BLK>>>(dist, vec, outer, idx_u, idx_v,
                                          q_mm, out, P);
    }
}

// round 15
// speedup vs baseline: 1.1807x; 1.1028x over previous
#include <cuda_runtime.h>
#include <cuda_fp16.h>
#include <cstdint>

// ---------------------------------------------------------------------------
// MLMM electrostatics.
// E(p) = KE * q_v * ( q_u*chi - chi^3*(r.mu) + chi^5 * sum(O * Q') )
// with Q' = Q - (trQ/3) I (traceless), Q'22 = -(Q'00+Q'11).
//
// Gather record per ML atom: 32 bytes, 32B-aligned (ONE L2 sector), fetched
// with a single Blackwell LDG.E.256 (ld.global.nc.v8.f32).
//
// R15 = R11 (111.1us champion) with two surgical changes:
//  - staging float4 loads use ld.global.cg.v4.f32 (L2-only) via inline asm
//    with identical register shape -- the 432MB vec/outer stream no longer
//    evicts the gather working set from L1. (R14's __ldcg intrinsics inflated
//    regs 32->40 and killed occupancy; this form does not.)
//  - __launch_bounds__(256, 8) pins regs <= 32 to guarantee occupancy.
// ---------------------------------------------------------------------------

#define NML_MAX 50000
#define KE_CONST 14.399645351950548f
#define CUTOFF_A 10.0f
#define BLK 256

// [2*u] : float4 {q, mu}; [2*u+1] : 8 fp16 Q' components
__device__ __align__(32) float4 g_packed[NML_MAX * 2];

__global__ void mlmm_prep_kernel(const float* __restrict__ q_ml,
                                 const float* __restrict__ mu,
                                 const float* __restrict__ Q,
                                 const float* __restrict__ e0,
                                 float* __restrict__ out,
                                 int nml) {
    int u = blockIdx.x * blockDim.x + threadIdx.x;
    if (u >= nml) return;

    out[u] = e0[u];

    float m0 = mu[3 * u + 0];
    float m1 = mu[3 * u + 1];
    float m2 = mu[3 * u + 2];

    float Qv[9];
#pragma unroll
    for (int k = 0; k < 9; k++) Qv[k] = Q[9 * u + k];
    float third_tr = (Qv[0] + Qv[4] + Qv[8]) * (1.0f / 3.0f);

    float t00 = Qv[0] - third_tr;
    float t11 = Qv[4] - third_tr;

    g_packed[2 * u + 0] = make_float4(q_ml[u], m0, m1, m2);

    __half2 h0 = __floats2half2_rn(t00,   Qv[1]);
    __half2 h1 = __floats2half2_rn(Qv[2], Qv[3]);
    __half2 h2 = __floats2half2_rn(t11,   Qv[5]);
    __half2 h3 = __floats2half2_rn(Qv[6], Qv[7]);

    uint4 packed;
    packed.x = *reinterpret_cast<unsigned int*>(&h0);
    packed.y = *reinterpret_cast<unsigned int*>(&h1);
    packed.z = *reinterpret_cast<unsigned int*>(&h2);
    packed.w = *reinterpret_cast<unsigned int*>(&h3);
    reinterpret_cast<uint4*>(g_packed)[2 * u + 1] = packed;
}

__device__ __forceinline__ float4 ldg_cg_v4(const float4* p) {
    float4 r;
    asm volatile("ld.global.cg.v4.f32 {%0, %1, %2, %3}, [%4];"
                 : "=f"(r.x), "=f"(r.y), "=f"(r.z), "=f"(r.w)
                 : "l"(p));
    return r;
}

__global__ void __launch_bounds__(BLK, 8)
mlmm_pair_kernel(const float* __restrict__ dist,
                 const float* __restrict__ vec,
                 const float* __restrict__ outer,
                 const int* __restrict__ idx_u,
                 const int* __restrict__ idx_v,
                 const float* __restrict__ q_mm,
                 float* __restrict__ out,
                 int n) {
    __shared__ __align__(16) float s_vec[BLK * 3];   // per-warp chunks: 96 floats
    __shared__ __align__(16) float s_out[BLK * 9];   // per-warp chunks: 288 floats

    int base = blockIdx.x * BLK;
    int cnt  = n - base;
    if (cnt > BLK) cnt = BLK;

    int tid  = threadIdx.x;
    int lane = tid & 31;
    int w    = tid >> 5;

    // ---- phase 1: per-thread loads, issued EARLY and in parallel ----
    int   i = base + tid;
    float d = 1e30f;
    int   u = 0, v = 0;
    if (tid < cnt) {
        d = dist[i];
        u = idx_u[i];   // unconditional: lines fetched by the warp anyway
        v = idx_v[i];
    }
    bool m = (d <= CUTOFF_A);

    float4 p0 = make_float4(0.f, 0.f, 0.f, 0.f);
    uint4  ph = make_uint4(0u, 0u, 0u, 0u);
    float  qv = 0.f;
    if (m) {
        // single 256-bit gather of the whole 32B record (Blackwell LDG.E.256)
        const float* rec = reinterpret_cast<const float*>(g_packed + 2 * u);
        float f0, f1, f2, f3, f4, f5, f6, f7;
        asm volatile(
            "ld.global.nc.v8.f32 {%0, %1, %2, %3, %4, %5, %6, %7}, [%8];"
            : "=f"(f0), "=f"(f1), "=f"(f2), "=f"(f3),
              "=f"(f4), "=f"(f5), "=f"(f6), "=f"(f7)
            : "l"(rec));
        p0 = make_float4(f0, f1, f2, f3);
        ph = make_uint4(__float_as_uint(f4), __float_as_uint(f5),
                        __float_as_uint(f6), __float_as_uint(f7));
        qv = KE_CONST * __ldg(q_mm + v);
    }

    // ---- phase 2: WARP-LOCAL staging of this warp's 32 pairs (L2-only) ----
    int wbase = base + 32 * w;       // first pair of this warp
    int wcnt  = cnt - 32 * w;        // pairs this warp owns
    if (wcnt > 32) wcnt = 32;

    float* sv = s_vec + 96 * w;      // 96 floats  (32 pairs x 3)
    float* so = s_out + 288 * w;     // 288 floats (32 pairs x 9)

    if (wcnt == 32) {
        const float4* v4 = (const float4*)(vec + 3 * wbase);
        if (lane < 24) reinterpret_cast<float4*>(sv)[lane] = ldg_cg_v4(v4 + lane);

        const float4* o4 = (const float4*)(outer + 9 * wbase);
#pragma unroll
        for (int t = lane; t < 72; t += 32)
            reinterpret_cast<float4*>(so)[t] = ldg_cg_v4(o4 + t);
    } else if (wcnt > 0) {
        for (int t = lane; t < wcnt * 3; t += 32) sv[t] = vec[3 * wbase + t];
        for (int t = lane; t < wcnt * 9; t += 32) so[t] = outer[9 * wbase + t];
    }
    __syncwarp();

    if (!m) return;

    // ---- phase 3: math + scatter ----
    float r0 = sv[3 * lane + 0];
    float r1 = sv[3 * lane + 1];
    float r2 = sv[3 * lane + 2];

    const float* op = so + 9 * lane;
    float o00 = op[0], o01 = op[1], o02 = op[2];
    float o10 = op[3], o11 = op[4], o12 = op[5];
    float o20 = op[6], o21 = op[7], o22 = op[8];

    float chi  = __fdividef(1.0f, d);
    float chi2 = chi * chi;
    float chi3 = chi2 * chi;
    float chi5 = chi3 * chi2;

    // charge-charge
    float e = p0.x * chi;

    // dipole: - chi^3 * (r . mu)
    e -= chi3 * (r0 * p0.y + r1 * p0.z + r2 * p0.w);

    // quadrupole: + chi^5 * sum(O * Q'), Q'22 = -(Q'00 + Q'11)
    float2 c0 = __half22float2(*reinterpret_cast<__half2*>(&ph.x)); // t00, Q01
    float2 c1 = __half22float2(*reinterpret_cast<__half2*>(&ph.y)); // Q02, Q10
    float2 c2 = __half22float2(*reinterpret_cast<__half2*>(&ph.z)); // t11, Q12
    float2 c3 = __half22float2(*reinterpret_cast<__half2*>(&ph.w)); // Q20, Q21

    float dot9 = c0.x * (o00 - o22)
               + c2.x * (o11 - o22)
               + c0.y * o01 + c1.x * o02 + c1.y * o10
               + c2.y * o12 + c3.x * o20 + c3.y * o21;
    e += chi5 * dot9;

    e *= qv;

    atomicAdd(out + u, e);
}

extern "C" void kernel_launch(void* const* d_in, const int* in_sizes, int n_in,
                              void* d_out, int out_size) {
    const float* q_ml  = (const float*)d_in[0];  // [NML]
    const float* q_mm  = (const float*)d_in[1];  // [NMM]
    const float* mu    = (const float*)d_in[2];  // [NML,3]
    const float* Q     = (const float*)d_in[3];  // [NML,3,3]
    const float* e0    = (const float*)d_in[4];  // [NML]
    const float* dist  = (const float*)d_in[5];  // [P]
    const float* vec   = (const float*)d_in[6];  // [P,3]
    const float* outer = (const float*)d_in[7];  // [P,3,3]
    const int*   idx_u = (const int*)d_in[8];    // [P] int32
    const int*   idx_v = (const int*)d_in[9];    // [P] int32

    float* out = (float*)d_out;

    int nml = in_sizes[0];
    int P   = in_sizes[5];

    {
        int threads = 256;
        int blocks  = (nml + threads - 1) / threads;
        mlmm_prep_kernel<<<blocks, threads>>>(q_ml, mu, Q, e0, out, nml);
    }
    {
        int blocks = (P + BLK - 1) / BLK;
        mlmm_pair_kernel<<<blocks, BLK>>>(dist, vec, outer, idx_u, idx_v,
                                          q_mm, out, P);
    }
}